// round 14
// baseline (speedup 1.0000x reference)
#include <cuda_runtime.h>
#include <math.h>

// Problem constants: N=16384, H=32, G=8, D=128, FF=2, R=4, GROUPS=4, NBAND=32
#define NTOK 16384
#define QK_TPB 16
#define W_TPB 8
#define NQK (NTOK / QK_TPB)   // 1024 qk blocks
#define NW  (NTOK / W_TPB)    // 2048 w blocks
#define NJOBS 20              // per warp: 4 K half-jobs + 16 Q token jobs
#define PFDIST 8              // in-loop L2 prefetch distance (job slots)

// Output layout in d_out (floats): index_q [N][4][128], index_k [N][128], weights [N][4]
#define OUT_Q_OFF ((size_t)0)
#define OUT_K_OFF ((size_t)NTOK * 512)
#define OUT_W_OFF ((size_t)NTOK * 512 + (size_t)NTOK * 128)

// smem: w path needs 8448 floats; qk path needs 32*33=1056 for padded proj.
#define SMEM_FLOATS 8448

// streaming (evict-first) accesses: all bulk inputs are read-once and all
// outputs are write-once -> keep L2 residency for the prefetch window only.
__device__ __forceinline__ void stcs2(float* p, float a, float b) {
    asm volatile("st.global.cs.v2.f32 [%0], {%1, %2};" :: "l"(p), "f"(a), "f"(b)
                 : "memory");
}
__device__ __forceinline__ float4 ldcs4(const float* p) {
    float4 r;
    asm volatile("ld.global.cs.v4.f32 {%0, %1, %2, %3}, [%4];"
                 : "=f"(r.x), "=f"(r.y), "=f"(r.z), "=f"(r.w) : "l"(p));
    return r;
}

// QK path (register-only fold, partial-sum exchange):
//   lane = band (bm = lane&15, fb = lane>>4).
//   float4 at (h = gh*4+gr, d = hf*64 + 4*bm):
//     x->(band=bm,feat=gh)  y->(band=16+bm,feat=gh)
//     z->(band=bm,feat=8+gh) w->(band=16+bm,feat=8+gh)
//   Lane loads gh = fb*4+j; computes own-band + partner-band (lane^16) partials
//   over those 8 feats; one shfl_xor(16) completes both bands.
// Block interleave: b%3==0 -> qk block b/3 ; else w block 2*(b/3)+(b%3-1).
// L2 prefetch: startup covers jobs 2..(PFDIST+1); in-loop distance PFDIST
//   (prefetch lands ~4 job slots before the consuming LDG at j+2 issue).

__global__ __launch_bounds__(256, 3) void fused_kernel(
    const float* __restrict__ q,
    const float* __restrict__ k,
    const float* __restrict__ v,
    const float* __restrict__ proj,   // [32][16][2]
    const float* __restrict__ vt,     // [32][128][4]
    float* __restrict__ out)
{
    extern __shared__ float smem[];
    const int tid = threadIdx.x;
    const int b    = blockIdx.x;
    const int bdiv = b / 3;
    const int bmod = b - bdiv * 3;

    if (bmod == 0) {
        // ================= QK path (block bdiv of NQK) =================
        float* SP = smem;                 // padded proj [32][33]
        const int lane = tid & 31;
        const int w    = tid >> 5;        // warp 0..7
        const int bm   = lane & 15;
        const int fb   = lane >> 4;       // band == lane
        const int gr   = w & 3;           // q group for this warp
        const int hf   = w >> 2;          // q half for this warp
        const int n0   = bdiv * QK_TPB;

        // stage proj into padded smem (coalesced LDG, conflict-free STS)
        {
            const float4 p = __ldg(&((const float4*)proj)[tid]);
            const int i0 = tid * 4;
            SP[(i0 >> 5) * 33 + (i0 & 31)]             = p.x;
            SP[((i0 + 1) >> 5) * 33 + ((i0 + 1) & 31)] = p.y;
            SP[((i0 + 2) >> 5) * 33 + ((i0 + 2) & 31)] = p.z;
            SP[((i0 + 3) >> 5) * 33 + ((i0 + 3) & 31)] = p.w;
        }

        const float* kb = k + (size_t)(n0 + w) * 1024 + fb * 512 + 4 * bm;
        const float* qb = q + (size_t)n0 * 4096 + (size_t)fb * 2048 +
                          gr * 128 + hf * 64 + 4 * bm;

        // job load: j<4 -> K (token +8*(j>>1), half j&1), else Q token j-4
        #define LOAD_JOB(j, dst)                                              \
            do {                                                              \
                if ((j) < 4) {                                                \
                    const float* b_ = kb + ((j) >> 1) * 8192 + ((j) & 1) * 64;\
                    _Pragma("unroll")                                         \
                    for (int i_ = 0; i_ < 4; i_++)                            \
                        (dst)[i_] = ldcs4(b_ + i_ * 128);                     \
                } else {                                                      \
                    const float* b_ = qb + (size_t)((j) - 4) * 4096;          \
                    _Pragma("unroll")                                         \
                    for (int i_ = 0; i_ < 4; i_++)                            \
                        (dst)[i_] = ldcs4(b_ + i_ * 512);                     \
                }                                                             \
            } while (0)

        // prefetch a job's four lines into L2 (no registers, no scoreboard)
        #define PREFETCH_JOB(j)                                               \
            do {                                                              \
                if ((j) < 4) {                                                \
                    const float* b_ = kb + ((j) >> 1) * 8192 + ((j) & 1) * 64;\
                    _Pragma("unroll")                                         \
                    for (int i_ = 0; i_ < 4; i_++)                            \
                        asm volatile("prefetch.global.L2 [%0];"               \
                                     :: "l"(b_ + i_ * 128));                  \
                } else {                                                      \
                    const float* b_ = qb + (size_t)((j) - 4) * 4096;          \
                    _Pragma("unroll")                                         \
                    for (int i_ = 0; i_ < 4; i_++)                            \
                        asm volatile("prefetch.global.L2 [%0];"               \
                                     :: "l"(b_ + i_ * 512));                  \
                }                                                             \
            } while (0)

        // issue loads for jobs 0,1 before the barrier (covers barrier latency)
        float4 A[4], B[4];
        LOAD_JOB(0, A);
        LOAD_JOB(1, B);
        PREFETCH_JOB(2);
        PREFETCH_JOB(3);
        PREFETCH_JOB(4);
        PREFETCH_JOB(5);
        PREFETCH_JOB(6);
        PREFETCH_JOB(7);
        PREFETCH_JOB(8);
        PREFETCH_JOB(9);

        __syncthreads();

        // coefficients from smem: own band row (lane) + partner row (lane^16)
        float4 cO[4], cX[4];
        {
            const float* ro = SP + lane * 33 + 8 * fb;
            const float* rx = SP + (lane ^ 16) * 33 + 8 * fb;
            #pragma unroll
            for (int m = 0; m < 2; m++) {
                cO[m]     = make_float4(ro[4*m], ro[4*m+1], ro[4*m+2], ro[4*m+3]);
                cO[2 + m] = make_float4(ro[16+4*m], ro[16+4*m+1], ro[16+4*m+2], ro[16+4*m+3]);
                cX[m]     = make_float4(rx[4*m], rx[4*m+1], rx[4*m+2], rx[4*m+3]);
                cX[2 + m] = make_float4(rx[16+4*m], rx[16+4*m+1], rx[16+4*m+2], rx[16+4*m+3]);
            }
        }

        #pragma unroll
        for (int j = 0; j < NJOBS; j++) {
            float4* Lc = (j & 1) ? B : A;
            float aO0 = 0.f, aO1 = 0.f, aX0 = 0.f, aX1 = 0.f;
            #pragma unroll
            for (int i = 0; i < 4; i++) {
                const float olo = fb ? Lc[i].y : Lc[i].x;
                const float ohi = fb ? Lc[i].w : Lc[i].z;
                const float xlo = fb ? Lc[i].x : Lc[i].y;
                const float xhi = fb ? Lc[i].z : Lc[i].w;
                const float4 fol = cO[i >> 1], foh = cO[2 + (i >> 1)];
                const float4 fxl = cX[i >> 1], fxh = cX[2 + (i >> 1)];
                if (i & 1) {
                    aO0 = fmaf(olo, fol.z, fmaf(ohi, foh.z, aO0));
                    aO1 = fmaf(olo, fol.w, fmaf(ohi, foh.w, aO1));
                    aX0 = fmaf(xlo, fxl.z, fmaf(xhi, fxh.z, aX0));
                    aX1 = fmaf(xlo, fxl.w, fmaf(xhi, fxh.w, aX1));
                } else {
                    aO0 = fmaf(olo, fol.x, fmaf(ohi, foh.x, aO0));
                    aO1 = fmaf(olo, fol.y, fmaf(ohi, foh.y, aO1));
                    aX0 = fmaf(xlo, fxl.x, fmaf(xhi, fxh.x, aX0));
                    aX1 = fmaf(xlo, fxl.y, fmaf(xhi, fxh.y, aX1));
                }
            }
            // prefetch job j+2 into the buffer just consumed; hint j+PFDIST to L2
            if (j + 2 < NJOBS) LOAD_JOB(j + 2, Lc);
            if (j + PFDIST < NJOBS && j >= 2) PREFETCH_JOB(j + PFDIST);

            const float a0 = aO0 + __shfl_xor_sync(0xffffffffu, aX0, 16);
            const float a1 = aO1 + __shfl_xor_sync(0xffffffffu, aX1, 16);

            float* o;
            if (j < 4) {
                o = out + OUT_K_OFF + (size_t)(n0 + w + (j >> 1) * 8) * 128 +
                    (j & 1) * 64 + lane * 2;
            } else {
                o = out + OUT_Q_OFF + (size_t)(n0 + j - 4) * 512 +
                    gr * 128 + hf * 64 + lane * 2;
            }
            stcs2(o, a0, a1);
        }
        #undef LOAD_JOB
        #undef PREFETCH_JOB
    } else {
        // ================= W path (block 2*bdiv + bmod-1 of NW) =================
        float* VS  = smem;            // [W_TPB][1024]
        float* RED = smem + 8192;     // [tok][g][t]

        const int wb   = 2 * bdiv + (bmod - 1);
        const int dseg = tid & 7;
        const int t    = (tid >> 3) & 3;
        const int g    = tid >> 5;
        const int h    = g * 4 + t;

        // vt slice in registers
        float4 wt[16];
        {
            const float4* vt4 = (const float4*)vt;
            #pragma unroll
            for (int i = 0; i < 16; i++)
                wt[i] = __ldg(&vt4[h * 128 + dseg + 8 * i]);
        }

        const int n0 = wb * W_TPB;

        // stage W_TPB v rows (coalesced, evict-first: v is read-once)
        {
            const float* v0 = v + (size_t)n0 * 1024;
            float4* vs4 = (float4*)VS;
            #pragma unroll
            for (int j = 0; j < W_TPB; j++)
                vs4[tid + 256 * j] = ldcs4(v0 + (tid + 256 * j) * 4);
        }
        __syncthreads();

        #pragma unroll
        for (int tok = 0; tok < W_TPB; tok++) {
            float4 a = make_float4(0.f, 0.f, 0.f, 0.f);
            float4 b2 = make_float4(0.f, 0.f, 0.f, 0.f);
            const float* vrow = VS + tok * 1024 + g * 128 + dseg;
            #pragma unroll
            for (int i = 0; i < 16; i += 2) {
                const float f0 = vrow[8 * i];
                const float f1 = vrow[8 * (i + 1)];
                a.x = fmaf(f0, wt[i].x, a.x);     b2.x = fmaf(f1, wt[i+1].x, b2.x);
                a.y = fmaf(f0, wt[i].y, a.y);     b2.y = fmaf(f1, wt[i+1].y, b2.y);
                a.z = fmaf(f0, wt[i].z, a.z);     b2.z = fmaf(f1, wt[i+1].z, b2.z);
                a.w = fmaf(f0, wt[i].w, a.w);     b2.w = fmaf(f1, wt[i+1].w, b2.w);
            }
            a.x += b2.x; a.y += b2.y; a.z += b2.z; a.w += b2.w;
            #pragma unroll
            for (int m = 1; m <= 4; m <<= 1) {
                a.x += __shfl_xor_sync(0xffffffffu, a.x, m);
                a.y += __shfl_xor_sync(0xffffffffu, a.y, m);
                a.z += __shfl_xor_sync(0xffffffffu, a.z, m);
                a.w += __shfl_xor_sync(0xffffffffu, a.w, m);
            }
            if (dseg == 0)
                RED[(tok * 8 + g) * 4 + t] =
                    a.x * a.x + a.y * a.y + a.z * a.z + a.w * a.w;
        }
        __syncthreads();

        if (tid < W_TPB * 4) {
            const int tok = tid >> 2;
            const int tt  = tid & 3;
            float s = 0.f;
            #pragma unroll
            for (int gg = 0; gg < 8; gg++) s += RED[(tok * 8 + gg) * 4 + tt];
            out[OUT_W_OFF + (size_t)(n0 + tok) * 4 + tt] = sqrtf(s);
        }
    }
}

extern "C" void kernel_launch(void* const* d_in, const int* in_sizes, int n_in,
                              void* d_out, int out_size)
{
    const float* q    = (const float*)d_in[0];   // [16384][32][128]
    const float* k    = (const float*)d_in[1];   // [16384][8][128]
    const float* v    = (const float*)d_in[2];   // [16384][8][128]
    const float* proj = (const float*)d_in[3];   // [32][16][2]
    const float* vt   = (const float*)d_in[4];   // [32][128][4]
    float* out = (float*)d_out;

    fused_kernel<<<NQK + NW, 256, SMEM_FLOATS * sizeof(float)>>>(
        q, k, v, proj, vt, out);
}

// round 15
// speedup vs baseline: 1.0516x; 1.0516x over previous
#include <cuda_runtime.h>
#include <math.h>

// Problem constants: N=16384, H=32, G=8, D=128, FF=2, R=4, GROUPS=4, NBAND=32
#define NTOK 16384
#define QK_TPB 16
#define W_TPB 8
#define NQK (NTOK / QK_TPB)   // 1024 qk blocks
#define NW  (NTOK / W_TPB)    // 2048 w blocks
#define NJOBS 20              // per warp: 4 K half-jobs + 16 Q token jobs
#define PFDIST 6              // in-loop L2 prefetch distance (measured optimum;
                              // 8 regressed: window exceeds L2 residency share)

// Output layout in d_out (floats): index_q [N][4][128], index_k [N][128], weights [N][4]
#define OUT_Q_OFF ((size_t)0)
#define OUT_K_OFF ((size_t)NTOK * 512)
#define OUT_W_OFF ((size_t)NTOK * 512 + (size_t)NTOK * 128)

// smem: w path needs 8448 floats; qk path needs 32*33=1056 for padded proj.
#define SMEM_FLOATS 8448

// streaming (evict-first) accesses: all bulk inputs are read-once and all
// outputs are write-once -> keep L2 residency for the prefetch window only.
__device__ __forceinline__ void stcs2(float* p, float a, float b) {
    asm volatile("st.global.cs.v2.f32 [%0], {%1, %2};" :: "l"(p), "f"(a), "f"(b)
                 : "memory");
}
__device__ __forceinline__ float4 ldcs4(const float* p) {
    float4 r;
    asm volatile("ld.global.cs.v4.f32 {%0, %1, %2, %3}, [%4];"
                 : "=f"(r.x), "=f"(r.y), "=f"(r.z), "=f"(r.w) : "l"(p));
    return r;
}

// QK path (register-only fold, partial-sum exchange):
//   lane = band (bm = lane&15, fb = lane>>4).
//   float4 at (h = gh*4+gr, d = hf*64 + 4*bm):
//     x->(band=bm,feat=gh)  y->(band=16+bm,feat=gh)
//     z->(band=bm,feat=8+gh) w->(band=16+bm,feat=8+gh)
//   Lane loads gh = fb*4+j; computes own-band + partner-band (lane^16) partials
//   over those 8 feats; one shfl_xor(16) completes both bands.
// Block interleave: b%3==0 -> qk block b/3 ; else w block 2*(b/3)+(b%3-1).
// L2 prefetch: startup covers jobs 2..7; in-loop distance 6.

__global__ __launch_bounds__(256, 3) void fused_kernel(
    const float* __restrict__ q,
    const float* __restrict__ k,
    const float* __restrict__ v,
    const float* __restrict__ proj,   // [32][16][2]
    const float* __restrict__ vt,     // [32][128][4]
    float* __restrict__ out)
{
    extern __shared__ float smem[];
    const int tid = threadIdx.x;
    const int b    = blockIdx.x;
    const int bdiv = b / 3;
    const int bmod = b - bdiv * 3;

    if (bmod == 0) {
        // ================= QK path (block bdiv of NQK) =================
        float* SP = smem;                 // padded proj [32][33]
        const int lane = tid & 31;
        const int w    = tid >> 5;        // warp 0..7
        const int bm   = lane & 15;
        const int fb   = lane >> 4;       // band == lane
        const int gr   = w & 3;           // q group for this warp
        const int hf   = w >> 2;          // q half for this warp
        const int n0   = bdiv * QK_TPB;

        // stage proj into padded smem (coalesced LDG, conflict-free STS)
        {
            const float4 p = __ldg(&((const float4*)proj)[tid]);
            const int i0 = tid * 4;
            SP[(i0 >> 5) * 33 + (i0 & 31)]             = p.x;
            SP[((i0 + 1) >> 5) * 33 + ((i0 + 1) & 31)] = p.y;
            SP[((i0 + 2) >> 5) * 33 + ((i0 + 2) & 31)] = p.z;
            SP[((i0 + 3) >> 5) * 33 + ((i0 + 3) & 31)] = p.w;
        }

        const float* kb = k + (size_t)(n0 + w) * 1024 + fb * 512 + 4 * bm;
        const float* qb = q + (size_t)n0 * 4096 + (size_t)fb * 2048 +
                          gr * 128 + hf * 64 + 4 * bm;

        // job load: j<4 -> K (token +8*(j>>1), half j&1), else Q token j-4
        #define LOAD_JOB(j, dst)                                              \
            do {                                                              \
                if ((j) < 4) {                                                \
                    const float* b_ = kb + ((j) >> 1) * 8192 + ((j) & 1) * 64;\
                    _Pragma("unroll")                                         \
                    for (int i_ = 0; i_ < 4; i_++)                            \
                        (dst)[i_] = ldcs4(b_ + i_ * 128);                     \
                } else {                                                      \
                    const float* b_ = qb + (size_t)((j) - 4) * 4096;          \
                    _Pragma("unroll")                                         \
                    for (int i_ = 0; i_ < 4; i_++)                            \
                        (dst)[i_] = ldcs4(b_ + i_ * 512);                     \
                }                                                             \
            } while (0)

        // prefetch a job's four lines into L2 (no registers, no scoreboard)
        #define PREFETCH_JOB(j)                                               \
            do {                                                              \
                if ((j) < 4) {                                                \
                    const float* b_ = kb + ((j) >> 1) * 8192 + ((j) & 1) * 64;\
                    _Pragma("unroll")                                         \
                    for (int i_ = 0; i_ < 4; i_++)                            \
                        asm volatile("prefetch.global.L2 [%0];"               \
                                     :: "l"(b_ + i_ * 128));                  \
                } else {                                                      \
                    const float* b_ = qb + (size_t)((j) - 4) * 4096;          \
                    _Pragma("unroll")                                         \
                    for (int i_ = 0; i_ < 4; i_++)                            \
                        asm volatile("prefetch.global.L2 [%0];"               \
                                     :: "l"(b_ + i_ * 512));                  \
                }                                                             \
            } while (0)

        // issue loads for jobs 0,1 before the barrier (covers barrier latency)
        float4 A[4], B[4];
        LOAD_JOB(0, A);
        LOAD_JOB(1, B);
        PREFETCH_JOB(2);
        PREFETCH_JOB(3);
        PREFETCH_JOB(4);
        PREFETCH_JOB(5);
        PREFETCH_JOB(6);
        PREFETCH_JOB(7);

        __syncthreads();

        // coefficients from smem: own band row (lane) + partner row (lane^16)
        float4 cO[4], cX[4];
        {
            const float* ro = SP + lane * 33 + 8 * fb;
            const float* rx = SP + (lane ^ 16) * 33 + 8 * fb;
            #pragma unroll
            for (int m = 0; m < 2; m++) {
                cO[m]     = make_float4(ro[4*m], ro[4*m+1], ro[4*m+2], ro[4*m+3]);
                cO[2 + m] = make_float4(ro[16+4*m], ro[16+4*m+1], ro[16+4*m+2], ro[16+4*m+3]);
                cX[m]     = make_float4(rx[4*m], rx[4*m+1], rx[4*m+2], rx[4*m+3]);
                cX[2 + m] = make_float4(rx[16+4*m], rx[16+4*m+1], rx[16+4*m+2], rx[16+4*m+3]);
            }
        }

        #pragma unroll
        for (int j = 0; j < NJOBS; j++) {
            float4* Lc = (j & 1) ? B : A;
            float aO0 = 0.f, aO1 = 0.f, aX0 = 0.f, aX1 = 0.f;
            #pragma unroll
            for (int i = 0; i < 4; i++) {
                const float olo = fb ? Lc[i].y : Lc[i].x;
                const float ohi = fb ? Lc[i].w : Lc[i].z;
                const float xlo = fb ? Lc[i].x : Lc[i].y;
                const float xhi = fb ? Lc[i].z : Lc[i].w;
                const float4 fol = cO[i >> 1], foh = cO[2 + (i >> 1)];
                const float4 fxl = cX[i >> 1], fxh = cX[2 + (i >> 1)];
                if (i & 1) {
                    aO0 = fmaf(olo, fol.z, fmaf(ohi, foh.z, aO0));
                    aO1 = fmaf(olo, fol.w, fmaf(ohi, foh.w, aO1));
                    aX0 = fmaf(xlo, fxl.z, fmaf(xhi, fxh.z, aX0));
                    aX1 = fmaf(xlo, fxl.w, fmaf(xhi, fxh.w, aX1));
                } else {
                    aO0 = fmaf(olo, fol.x, fmaf(ohi, foh.x, aO0));
                    aO1 = fmaf(olo, fol.y, fmaf(ohi, foh.y, aO1));
                    aX0 = fmaf(xlo, fxl.x, fmaf(xhi, fxh.x, aX0));
                    aX1 = fmaf(xlo, fxl.y, fmaf(xhi, fxh.y, aX1));
                }
            }
            // prefetch job j+2 into the buffer just consumed; hint j+PFDIST to L2
            if (j + 2 < NJOBS) LOAD_JOB(j + 2, Lc);
            if (j + PFDIST < NJOBS && j >= 2) PREFETCH_JOB(j + PFDIST);

            const float a0 = aO0 + __shfl_xor_sync(0xffffffffu, aX0, 16);
            const float a1 = aO1 + __shfl_xor_sync(0xffffffffu, aX1, 16);

            float* o;
            if (j < 4) {
                o = out + OUT_K_OFF + (size_t)(n0 + w + (j >> 1) * 8) * 128 +
                    (j & 1) * 64 + lane * 2;
            } else {
                o = out + OUT_Q_OFF + (size_t)(n0 + j - 4) * 512 +
                    gr * 128 + hf * 64 + lane * 2;
            }
            stcs2(o, a0, a1);
        }
        #undef LOAD_JOB
        #undef PREFETCH_JOB
    } else {
        // ================= W path (block 2*bdiv + bmod-1 of NW) =================
        float* VS  = smem;            // [W_TPB][1024]
        float* RED = smem + 8192;     // [tok][g][t]

        const int wb   = 2 * bdiv + (bmod - 1);
        const int dseg = tid & 7;
        const int t    = (tid >> 3) & 3;
        const int g    = tid >> 5;
        const int h    = g * 4 + t;

        // vt slice in registers
        float4 wt[16];
        {
            const float4* vt4 = (const float4*)vt;
            #pragma unroll
            for (int i = 0; i < 16; i++)
                wt[i] = __ldg(&vt4[h * 128 + dseg + 8 * i]);
        }

        const int n0 = wb * W_TPB;

        // stage W_TPB v rows (coalesced, evict-first: v is read-once)
        {
            const float* v0 = v + (size_t)n0 * 1024;
            float4* vs4 = (float4*)VS;
            #pragma unroll
            for (int j = 0; j < W_TPB; j++)
                vs4[tid + 256 * j] = ldcs4(v0 + (tid + 256 * j) * 4);
        }
        __syncthreads();

        #pragma unroll
        for (int tok = 0; tok < W_TPB; tok++) {
            float4 a = make_float4(0.f, 0.f, 0.f, 0.f);
            float4 b2 = make_float4(0.f, 0.f, 0.f, 0.f);
            const float* vrow = VS + tok * 1024 + g * 128 + dseg;
            #pragma unroll
            for (int i = 0; i < 16; i += 2) {
                const float f0 = vrow[8 * i];
                const float f1 = vrow[8 * (i + 1)];
                a.x = fmaf(f0, wt[i].x, a.x);     b2.x = fmaf(f1, wt[i+1].x, b2.x);
                a.y = fmaf(f0, wt[i].y, a.y);     b2.y = fmaf(f1, wt[i+1].y, b2.y);
                a.z = fmaf(f0, wt[i].z, a.z);     b2.z = fmaf(f1, wt[i+1].z, b2.z);
                a.w = fmaf(f0, wt[i].w, a.w);     b2.w = fmaf(f1, wt[i+1].w, b2.w);
            }
            a.x += b2.x; a.y += b2.y; a.z += b2.z; a.w += b2.w;
            #pragma unroll
            for (int m = 1; m <= 4; m <<= 1) {
                a.x += __shfl_xor_sync(0xffffffffu, a.x, m);
                a.y += __shfl_xor_sync(0xffffffffu, a.y, m);
                a.z += __shfl_xor_sync(0xffffffffu, a.z, m);
                a.w += __shfl_xor_sync(0xffffffffu, a.w, m);
            }
            if (dseg == 0)
                RED[(tok * 8 + g) * 4 + t] =
                    a.x * a.x + a.y * a.y + a.z * a.z + a.w * a.w;
        }
        __syncthreads();

        if (tid < W_TPB * 4) {
            const int tok = tid >> 2;
            const int tt  = tid & 3;
            float s = 0.f;
            #pragma unroll
            for (int gg = 0; gg < 8; gg++) s += RED[(tok * 8 + gg) * 4 + tt];
            out[OUT_W_OFF + (size_t)(n0 + tok) * 4 + tt] = sqrtf(s);
        }
    }
}

extern "C" void kernel_launch(void* const* d_in, const int* in_sizes, int n_in,
                              void* d_out, int out_size)
{
    const float* q    = (const float*)d_in[0];   // [16384][32][128]
    const float* k    = (const float*)d_in[1];   // [16384][8][128]
    const float* v    = (const float*)d_in[2];   // [16384][8][128]
    const float* proj = (const float*)d_in[3];   // [32][16][2]
    const float* vt   = (const float*)d_in[4];   // [32][128][4]
    float* out = (float*)d_out;

    fused_kernel<<<NQK + NW, 256, SMEM_FLOATS * sizeof(float)>>>(
        q, k, v, proj, vt, out);
}